// round 1
// baseline (speedup 1.0000x reference)
#include <cuda_runtime.h>
#include <float.h>

// Problem constants (validated against in_sizes at launch)
#define KMAX   256
#define BMAX   8
#define GUIDE  4096

// Scratch (no allocation allowed): packed segments per batch + shared guide table.
// Segment s (s in [0..K]) covers x in [segE[s], segE[s+1]):
//   s = 0      : (-FLT_MAX, c[0],   0,            E[0])      -> low clamp
//   s = 1..K-1 : ( E[s-1],  c[s-1], slope(s-1,s), E[s])      -> interior
//   s = K      : ( E[K-1],  c[K-1], 0,            FLT_MAX)   -> high clamp
__device__ float4 g_seg[BMAX][KMAX + 2];
__device__ int    g_guide[GUIDE];

// ---------------------------------------------------------------------------
// Kernel 1: per-batch CRF curve + packed segment table. Grid = B, 256 threads.
// ---------------------------------------------------------------------------
__global__ void build_segments(const float* __restrict__ w,    // [B, NB]
                               const float* __restrict__ E,    // [K]
                               const float* __restrict__ f0,   // [K]
                               const float* __restrict__ Hb,   // [K, NB]
                               int K, int NB)
{
    const int b = blockIdx.x;
    const int k = threadIdx.x;

    __shared__ float c[KMAX];
    __shared__ float Es[KMAX];

    if (k < K) {
        float acc = f0[k];
        const float* hrow = Hb + (long long)k * NB;
        const float* wrow = w  + (long long)b * NB;
        #pragma unroll 5
        for (int n = 0; n < NB; n++)
            acc = fmaf(hrow[n], wrow[n], acc);
        c[k]  = acc;
        Es[k] = E[k];
    }
    __syncthreads();

    if (k == 0) {
        g_seg[b][0] = make_float4(-FLT_MAX, c[0],     0.0f, Es[0]);
        g_seg[b][K] = make_float4(Es[K - 1], c[K - 1], 0.0f, FLT_MAX);
    }
    if (k >= 1 && k <= K - 1) {
        const float e0 = Es[k - 1], e1 = Es[k];
        const float slope = (c[k] - c[k - 1]) / (e1 - e0);
        g_seg[b][k] = make_float4(e0, c[k - 1], slope, e1);
    }
}

// ---------------------------------------------------------------------------
// Kernel 2: uniform guide table (batch-independent).
// g_guide[j] = #{ i : E[i] <= j/GUIDE } = starting segment index for bin j.
// ---------------------------------------------------------------------------
__global__ void build_guide(const float* __restrict__ E, int K)
{
    const int j = blockIdx.x * blockDim.x + threadIdx.x;
    if (j >= GUIDE) return;
    const float v = (float)j * (1.0f / (float)GUIDE);
    int lo = 0, hi = K;                 // first index with E[idx] > v
    while (lo < hi) {
        const int mid = (lo + hi) >> 1;
        if (E[mid] <= v) lo = mid + 1; else hi = mid;
    }
    g_guide[j] = lo;
}

// ---------------------------------------------------------------------------
// Kernel 3: streaming apply. Grid = (GRIDX, B), 256 threads, float4 I/O.
// ---------------------------------------------------------------------------
__device__ __forceinline__ float interp1(float x,
                                         const int*    __restrict__ gde,
                                         const float4* __restrict__ seg)
{
    int j = (int)(x * (float)GUIDE);
    j = min(max(j, 0), GUIDE - 1);
    int s = gde[j];
    float4 sg = seg[s];
    // rare backward guard (float rounding of x*GUIDE at a bin edge)
    while (sg.x > x) { --s; sg = seg[s]; }
    // forward advance: expected ~0.06 iterations (256 knots / 4096 bins)
    while (x >= sg.w) { ++s; sg = seg[s]; }
    return __saturatef(fmaf(x - sg.x, sg.z, sg.y));
}

__global__ void __launch_bounds__(256, 8)
tmo_apply(const float* __restrict__ img, float* __restrict__ out,
          int npix, int K)
{
    __shared__ int    guide_s[GUIDE];
    __shared__ float4 seg_s[KMAX + 2];

    const int b = blockIdx.y;

    for (int i = threadIdx.x; i < GUIDE; i += blockDim.x)
        guide_s[i] = g_guide[i];
    for (int i = threadIdx.x; i <= K; i += blockDim.x)
        seg_s[i] = g_seg[b][i];
    __syncthreads();

    const long long base = (long long)b * (long long)npix;
    const float4* __restrict__ in4  = (const float4*)(img + base);
    float4*       __restrict__ out4 = (float4*)(out + base);

    const int n4     = npix >> 2;
    const int stride = gridDim.x * blockDim.x;

    for (int i = blockIdx.x * blockDim.x + threadIdx.x; i < n4; i += stride) {
        const float4 x = in4[i];
        float4 y;
        y.x = interp1(x.x, guide_s, seg_s);
        y.y = interp1(x.y, guide_s, seg_s);
        y.z = interp1(x.z, guide_s, seg_s);
        y.w = interp1(x.w, guide_s, seg_s);
        out4[i] = y;
    }

    // scalar tail (npix not divisible by 4) — handled by blockIdx.x == 0
    if (blockIdx.x == 0) {
        for (int i = (n4 << 2) + threadIdx.x; i < npix; i += blockDim.x)
            out[base + i] = interp1(img[base + i], guide_s, seg_s);
    }
}

// ---------------------------------------------------------------------------
// Launch contract
// Inputs (metadata order): hdr_image [B,C,H,W] f32, weights_w [B,NB] f32,
//                          E_samples [K] f32, f0_mean [K] f32, H_basis [K,NB] f32
// Output: [B,C,H,W] f32
// ---------------------------------------------------------------------------
extern "C" void kernel_launch(void* const* d_in, const int* in_sizes, int n_in,
                              void* d_out, int out_size)
{
    const float* img = (const float*)d_in[0];
    const float* w   = (const float*)d_in[1];
    const float* E   = (const float*)d_in[2];
    const float* f0  = (const float*)d_in[3];
    const float* Hb  = (const float*)d_in[4];
    float* out = (float*)d_out;

    const int K    = in_sizes[2];                 // 256
    const int NB   = in_sizes[4] / K;             // 25
    const int B    = in_sizes[1] / NB;            // 8
    const int npix = in_sizes[0] / B;             // C*H*W = 6,220,800

    build_segments<<<B, 256>>>(w, E, f0, Hb, K, NB);
    build_guide<<<(GUIDE + 255) / 256, 256>>>(E, K);

    dim3 grid(148, B);                            // 8 CTAs/SM, one full wave
    tmo_apply<<<grid, 256>>>(img, out, npix, K);
}